// round 6
// baseline (speedup 1.0000x reference)
#include <cuda_runtime.h>
#include <cstdint>

#define BS      512
#define DIM     128
#define POS_K   32
#define NUM_NEG 1024
#define INV_TEMP (1.0f / 0.07f)

#define NBLK    444                       // 148 SMs * 3 resident blocks
#define N_ITEMS 2048                      // (b,q) units: 512 b * 4 q of 256 negs
#define D_ST    4                         // per-warp ring depth (stages)
// per warp-stage: 4 rows * 512B = 2 KB. warp ring = D_ST*2KB. block ring = 8*D_ST*2KB = 64KB

// Output layout (flattened tuple, float32):
#define O0 0          // inst_v2a_pos [512,1]
#define O1 512        // inst_v2a_neg [512,1024]
#define O2 524800     // inst_a2v_pos [512,1]
#define O3 525312     // inst_a2v_neg [512,1024]
#define O4 1049600    // pos_v2v_pos  [512,32]
#define O5 1065984    // pos_v2v_neg  [512,1024]
#define O6 1590272    // pos_a2a_pos  [512,32]
#define O7 1606656    // pos_a2a_neg  [512,1024]

#define FULL 0xffffffffu

__device__ __forceinline__ float warp_sum(float x) {
#pragma unroll
    for (int o = 16; o; o >>= 1) x += __shfl_xor_sync(FULL, x, o);
    return x;
}

__device__ __forceinline__ float dot4(float4 x, float4 y) {
    return x.x * y.x + x.y * y.y + x.z * y.z + x.w * y.w;
}

__device__ __forceinline__ void grp8_sum2(float& a, float& b) {
#pragma unroll
    for (int o = 4; o; o >>= 1) {
        a += __shfl_xor_sync(FULL, a, o);
        b += __shfl_xor_sync(FULL, b, o);
    }
}

__device__ __forceinline__ float4 shfl_f4(float4 v, int src) {
    float4 r;
    r.x = __shfl_sync(FULL, v.x, src);
    r.y = __shfl_sync(FULL, v.y, src);
    r.z = __shfl_sync(FULL, v.z, src);
    r.w = __shfl_sync(FULL, v.w, src);
    return r;
}

__device__ __forceinline__ void cp_async16(uint32_t dst_smem, const void* src) {
    asm volatile("cp.async.cg.shared.global [%0], [%1], 16;\n"
                 :: "r"(dst_smem), "l"(src) : "memory");
}
__device__ __forceinline__ void cp_commit() {
    asm volatile("cp.async.commit_group;\n" ::: "memory");
}
template <int N>
__device__ __forceinline__ void cp_wait() {
    asm volatile("cp.async.wait_group %0;\n" :: "n"(N) : "memory");
}

// normalize this warp's copy of a 128-float vector (lane holds float4 chunk `lane`),
// then extract the 4 slices this lane needs (chunks c, c+8, c+16, c+24).
__device__ __forceinline__ void norm_slices(float4 raw, int c,
                                            float4& s0, float4& s1,
                                            float4& s2, float4& s3) {
    float ss = warp_sum(dot4(raw, raw));
    float inv = 1.0f / fmaxf(sqrtf(ss), 1e-12f);
    float4 n = make_float4(raw.x * inv, raw.y * inv, raw.z * inv, raw.w * inv);
    s0 = shfl_f4(n, c);
    s1 = shfl_f4(n, c + 8);
    s2 = shfl_f4(n, c + 16);
    s3 = shfl_f4(n, c + 24);
}

__global__ __launch_bounds__(256, 3)
void avid_cma_kernel(const float* __restrict__ video,
                     const float* __restrict__ audio,
                     const float4* __restrict__ m1,
                     const float4* __restrict__ m2,
                     const int* __restrict__ y,
                     const int* __restrict__ pos_idx,
                     const int* __restrict__ neg_idx,
                     float* __restrict__ out)
{
    extern __shared__ char ring[];                 // 8 warps * D_ST * 2048 B
    __shared__ float sout[8][4][32];               // per-warp output staging

    const int tid  = threadIdx.x;
    const int lane = tid & 31;
    const int w    = tid >> 5;
    const int c    = lane & 7;                     // float4-chunk within row
    const int r    = lane >> 3;                    // 8-lane group = row slot
    char* const wring = ring + (size_t)w * (D_ST * 2048);

    const int n_items = (N_ITEMS - blockIdx.x + NBLK - 1) / NBLK;
    const int total_st = n_items * 16;

    // ---------- item 0 state ----------
    int u = blockIdx.x;
    int b = u >> 2, q = u & 3;
    int idx_cur = __ldg(neg_idx + (size_t)b * NUM_NEG + q * 256 + w * 32 + lane);
    float4 v0, v1, v2, v3, a0, a1, a2, a3;
    {
        float4 vr = reinterpret_cast<const float4*>(video)[b * 32 + lane];
        float4 ar = reinterpret_cast<const float4*>(audio)[b * 32 + lane];
        norm_slices(vr, c, v0, v1, v2, v3);
        norm_slices(ar, c, a0, a1, a2, a3);
    }

    // ---------- prologue: issue stages 0..D_ST-2 of item 0 ----------
#pragma unroll
    for (int g = 0; g < D_ST - 1; ++g) {
        const int s = g & 15;
#pragma unroll
        for (int i = 0; i < 4; ++i) {
            const int ni = __shfl_sync(FULL, idx_cur, 2 * s + (i >> 1));
            const float4* src = ((i & 1) ? m2 : m1) + (size_t)ni * 32 + lane;
            uint32_t dst = (uint32_t)__cvta_generic_to_shared(
                wring + (g % D_ST) * 2048 + i * 512 + lane * 16);
            cp_async16(dst, src);
        }
        cp_commit();
    }

    // ---------- pos + self dots for b_p = blockIdx.x (+NBLK if < 68) ----------
    for (int bp = blockIdx.x; bp < BS; bp += NBLK) {
        float4 pv0, pv1, pv2, pv3, pa0, pa1, pa2, pa3;
        {
            float4 vr = reinterpret_cast<const float4*>(video)[bp * 32 + lane];
            float4 ar = reinterpret_cast<const float4*>(audio)[bp * 32 + lane];
            norm_slices(vr, c, pv0, pv1, pv2, pv3);
            norm_slices(ar, c, pa0, pa1, pa2, pa3);
        }
        const int j  = w * 4 + r;
        const int pi = __ldg(pos_idx + (size_t)bp * POS_K + j);
        const float4* p1 = m1 + (size_t)pi * 32 + c;
        const float4* p2 = m2 + (size_t)pi * 32 + c;
        float dvv = dot4(p1[0], pv0) + dot4(p1[8], pv1) + dot4(p1[16], pv2) + dot4(p1[24], pv3);
        float daa = dot4(p2[0], pa0) + dot4(p2[8], pa1) + dot4(p2[16], pa2) + dot4(p2[24], pa3);
        grp8_sum2(dvv, daa);
        if (c == 0) {
            out[O4 + (size_t)bp * POS_K + j] = dvv * INV_TEMP;
            out[O6 + (size_t)bp * POS_K + j] = daa * INV_TEMP;
        }
        if (w == 0 && r < 2) {
            const int yi = __ldg(y + bp);
            const float4* p = (r == 0 ? m1 : m2) + (size_t)yi * 32 + c;
            float d;
            if (r == 0) d = dot4(p[0], pa0) + dot4(p[8], pa1) + dot4(p[16], pa2) + dot4(p[24], pa3);
            else        d = dot4(p[0], pv0) + dot4(p[8], pv1) + dot4(p[16], pv2) + dot4(p[24], pv3);
#pragma unroll
            for (int o = 4; o; o >>= 1) d += __shfl_xor_sync(0x0000ffffu, d, o);
            if (c == 0) {
                if (r == 0) out[O2 + bp] = d * INV_TEMP;
                else        out[O0 + bp] = d * INV_TEMP;
            }
        }
    }

    // ---------- main persistent loop ----------
    for (int it = 0; it < n_items; ++it) {
        // prefetch next item
        const int un = u + NBLK;
        const bool hasn = (un < N_ITEMS);
        int idx_next = 0;
        float4 vrn = make_float4(0, 0, 0, 0), arn = vrn;
        if (hasn) {
            const int bn = un >> 2, qn = un & 3;
            idx_next = __ldg(neg_idx + (size_t)bn * NUM_NEG + qn * 256 + w * 32 + lane);
            vrn = reinterpret_cast<const float4*>(video)[bn * 32 + lane];
            arn = reinterpret_cast<const float4*>(audio)[bn * 32 + lane];
        }

        for (int s = 0; s < 16; ++s) {
            // issue global stage gi (D_ST-1 ahead), may belong to next item
            const int gi = it * 16 + s + (D_ST - 1);
            if (gi < total_st) {
                const int it2 = gi >> 4;
                const int s2  = gi & 15;
                const int idxreg = (it2 == it) ? idx_cur : idx_next;
#pragma unroll
                for (int i = 0; i < 4; ++i) {
                    const int ni = __shfl_sync(FULL, idxreg, 2 * s2 + (i >> 1));
                    const float4* src = ((i & 1) ? m2 : m1) + (size_t)ni * 32 + lane;
                    uint32_t dst = (uint32_t)__cvta_generic_to_shared(
                        wring + (gi % D_ST) * 2048 + i * 512 + lane * 16);
                    cp_async16(dst, src);
                }
            }
            cp_commit();

            cp_wait<D_ST - 2>();               // stage (it*16+s) landed for this warp
            __syncwarp();

            // compute: group r handles row r of this stage
            const float4* buf = reinterpret_cast<const float4*>(
                wring + ((it * 16 + s) % D_ST) * 2048) + (size_t)r * 32;
            const float4 x0 = buf[c], x1 = buf[c + 8], x2 = buf[c + 16], x3 = buf[c + 24];
            float dv = dot4(x0, v0) + dot4(x1, v1) + dot4(x2, v2) + dot4(x3, v3);
            float da = dot4(x0, a0) + dot4(x1, a1) + dot4(x2, a2) + dot4(x3, a3);
            grp8_sum2(dv, da);
            if (c == 0) {
                const int j = 2 * s + (r >> 1);        // 0..31 within warp slice
                if ((r & 1) == 0) {                    // m1 row: ·a -> O3, ·v -> O5
                    sout[w][1][j] = da * INV_TEMP;
                    sout[w][2][j] = dv * INV_TEMP;
                } else {                               // m2 row: ·v -> O1, ·a -> O7
                    sout[w][0][j] = dv * INV_TEMP;
                    sout[w][3][j] = da * INV_TEMP;
                }
            }
        }

        // flush this warp's 32 negs (coalesced 128B per array)
        __syncwarp();
        {
            const size_t base = (size_t)b * NUM_NEG + q * 256 + w * 32 + lane;
            out[O1 + base] = sout[w][0][lane];
            out[O3 + base] = sout[w][1][lane];
            out[O5 + base] = sout[w][2][lane];
            out[O7 + base] = sout[w][3][lane];
        }
        __syncwarp();

        // rotate item state
        if (hasn) {
            u = un; b = u >> 2; q = u & 3;
            idx_cur = idx_next;
            norm_slices(vrn, c, v0, v1, v2, v3);
            norm_slices(arn, c, a0, a1, a2, a3);
        }
    }
}

extern "C" void kernel_launch(void* const* d_in, const int* in_sizes, int n_in,
                              void* d_out, int out_size)
{
    const float* video = (const float*)d_in[0];
    const float* audio = (const float*)d_in[1];
    const float4* m1   = (const float4*)d_in[2];
    const float4* m2   = (const float4*)d_in[3];
    const int* y       = (const int*)d_in[4];
    const int* pos_idx = (const int*)d_in[5];
    const int* neg_idx = (const int*)d_in[6];
    float* out         = (float*)d_out;

    const int dyn_smem = 8 * D_ST * 2048;   // 64 KB
    cudaFuncSetAttribute(avid_cma_kernel,
                         cudaFuncAttributeMaxDynamicSharedMemorySize, dyn_smem);

    avid_cma_kernel<<<NBLK, 256, dyn_smem>>>(video, audio, m1, m2, y,
                                             pos_idx, neg_idx, out);
}